// round 1
// baseline (speedup 1.0000x reference)
#include <cuda_runtime.h>
#include <math.h>

#define Bb   16
#define Nn   512
#define Dd   512
#define Hh   8
#define HDm  64
#define MR   (Bb*Nn)     // 8192 rows
#define DFF  2048

// ---------------- scratch (static device globals; no allocation) ----------------
__device__ float g_h1 [MR*Dd];
__device__ float g_Qb [MR*Dd];      // (B,H,N,HD)
__device__ float g_Kb [MR*Dd];
__device__ float g_Vb [MR*Dd];
__device__ float g_S  [Bb*Hh*Nn*Nn];  // 33.5M floats
__device__ float g_O  [MR*Dd];      // (B,N,D)
__device__ float g_x1 [MR*Dd];
__device__ float g_h2 [MR*Dd];
__device__ float g_mid[MR*DFF];
__device__ int   g_adj_is32;

// ---------------- adj dtype detection (int32 vs int64) ----------------
// If adj is int64 (little endian, values 0..4), every odd int32 word is 0.
// If adj is int32, odd positions are adj values, nonzero w.p. ~1.
__global__ void detect_adj_kernel(const int* __restrict__ a) {
    __shared__ int flag;
    if (threadIdx.x == 0) flag = 0;
    __syncthreads();
    for (int i = threadIdx.x; i < 8192; i += blockDim.x)
        if (a[2*i + 1] != 0) flag = 1;
    __syncthreads();
    if (threadIdx.x == 0) g_adj_is32 = flag;
}

// ---------------- LayerNorm: one block per row of 512 ----------------
__global__ __launch_bounds__(256) void ln_kernel(
    const float* __restrict__ X, const float* __restrict__ g,
    const float* __restrict__ beta, float* __restrict__ Y)
{
    int row = blockIdx.x;
    const float* x = X + (size_t)row * Dd;
    int tid = threadIdx.x;
    float v0 = x[tid], v1 = x[tid + 256];

    __shared__ float red1[8], red2[8];
    float s = v0 + v1;
    #pragma unroll
    for (int o = 16; o; o >>= 1) s += __shfl_xor_sync(0xffffffffu, s, o);
    if ((tid & 31) == 0) red1[tid >> 5] = s;
    __syncthreads();
    float tot = red1[0]+red1[1]+red1[2]+red1[3]+red1[4]+red1[5]+red1[6]+red1[7];
    float mu = tot * (1.0f / 512.0f);

    float d0 = v0 - mu, d1 = v1 - mu;
    float s2 = d0*d0 + d1*d1;
    #pragma unroll
    for (int o = 16; o; o >>= 1) s2 += __shfl_xor_sync(0xffffffffu, s2, o);
    if ((tid & 31) == 0) red2[tid >> 5] = s2;
    __syncthreads();
    float tot2 = red2[0]+red2[1]+red2[2]+red2[3]+red2[4]+red2[5]+red2[6]+red2[7];
    float inv = rsqrtf(tot2 * (1.0f / 512.0f) + 1e-5f);

    Y[(size_t)row*Dd + tid      ] = d0 * inv * g[tid      ] + beta[tid      ];
    Y[(size_t)row*Dd + tid + 256] = d1 * inv * g[tid + 256] + beta[tid + 256];
}

// ---------------- generic 128x128x8 SGEMM, C = A(MxK) @ W(KxN), fused epilogues --
// MODE 0: QKV   -> out[((b*H+h)*N+n)*HD+d] = acc + bias[c]
// MODE 1: OPROJ -> out[r*N+c] = acc + bias[c] + res[r*N+c]
// MODE 2: FFN1  -> out[r*N+c] = gelu(acc + bias[c])   (exact erf gelu)
// MODE 3: FFN2  -> out[r*N+c] = (acc + bias[c] + res[r*N+c]) * mask[r]
template<int MODE>
__global__ __launch_bounds__(256) void sgemm_kernel(
    const float* __restrict__ A, const float* __restrict__ W,
    const float* __restrict__ bias, const float* __restrict__ res,
    const float* __restrict__ mask, float* __restrict__ C,
    int M, int N, int K)
{
    __shared__ float As[8][128];
    __shared__ float Bs[8][128];
    int tid = threadIdx.x;
    int bm = blockIdx.y * 128;
    int bn = blockIdx.x * 128;

    int arow = tid >> 1, acol = (tid & 1) * 4;     // A tile 128x8
    int brow = tid >> 5, bcol = (tid & 31) * 4;    // W tile 8x128
    int rm = (tid >> 4) * 8, cn = (tid & 15) * 8;

    const float* Aptr = A + (size_t)(bm + arow) * K + acol;
    const float* Wptr = W + (size_t)brow * N + bn + bcol;

    float acc[8][8];
    #pragma unroll
    for (int i = 0; i < 8; i++)
        #pragma unroll
        for (int j = 0; j < 8; j++) acc[i][j] = 0.0f;

    for (int k0 = 0; k0 < K; k0 += 8) {
        float4 av = *reinterpret_cast<const float4*>(Aptr + k0);
        As[acol+0][arow] = av.x; As[acol+1][arow] = av.y;
        As[acol+2][arow] = av.z; As[acol+3][arow] = av.w;
        float4 bv = *reinterpret_cast<const float4*>(Wptr + (size_t)k0 * N);
        *reinterpret_cast<float4*>(&Bs[brow][bcol]) = bv;
        __syncthreads();
        #pragma unroll
        for (int k = 0; k < 8; k++) {
            float4 a0 = *reinterpret_cast<const float4*>(&As[k][rm]);
            float4 a1 = *reinterpret_cast<const float4*>(&As[k][rm+4]);
            float4 b0 = *reinterpret_cast<const float4*>(&Bs[k][cn]);
            float4 b1 = *reinterpret_cast<const float4*>(&Bs[k][cn+4]);
            float ar[8] = {a0.x,a0.y,a0.z,a0.w,a1.x,a1.y,a1.z,a1.w};
            float br[8] = {b0.x,b0.y,b0.z,b0.w,b1.x,b1.y,b1.z,b1.w};
            #pragma unroll
            for (int i = 0; i < 8; i++)
                #pragma unroll
                for (int j = 0; j < 8; j++)
                    acc[i][j] = fmaf(ar[i], br[j], acc[i][j]);
        }
        __syncthreads();
    }

    #pragma unroll
    for (int i = 0; i < 8; i++) {
        int r = bm + rm + i;
        float mr = 0.0f, resv = 0.0f;
        if (MODE == 3) mr = mask[r];
        #pragma unroll
        for (int j = 0; j < 8; j++) {
            int c = bn + cn + j;
            float v = acc[i][j] + bias[c];
            if (MODE == 0) {
                int b = r >> 9, n = r & 511, h = c >> 6, d = c & 63;
                C[(size_t)(((b*Hh + h) << 9) + n) * HDm + d] = v;
            } else if (MODE == 1) {
                C[(size_t)r * N + c] = v + res[(size_t)r * N + c];
            } else if (MODE == 2) {
                C[(size_t)r * N + c] = 0.5f * v * (1.0f + erff(v * 0.70710678118654752f));
            } else {
                resv = res[(size_t)r * N + c];
                C[(size_t)r * N + c] = (v + resv) * mr;
            }
        }
    }
}

// ---------------- attention scores: S = Q @ K^T / 8 + edge_bias, masked ----------
// 128x128 tile over (q,k), reduce dim = 64
__global__ __launch_bounds__(256) void score_kernel(
    const float* __restrict__ Q, const float* __restrict__ Kt,
    const float* __restrict__ ebias, const int* __restrict__ adj32,
    const float* __restrict__ mask, float* __restrict__ S)
{
    __shared__ float As[8][128];
    __shared__ float Bs[8][128];
    int tid = threadIdx.x;
    int bh = blockIdx.z, b = bh >> 3, h = bh & 7;
    int qt = blockIdx.y * 128, kt = blockIdx.x * 128;
    const float* Qb = Q  + (size_t)(bh * Nn + qt) * HDm;
    const float* Kb = Kt + (size_t)(bh * Nn + kt) * HDm;

    int lrow = tid >> 1, lcol = (tid & 1) * 4;
    int rm = (tid >> 4) * 8, cn = (tid & 15) * 8;

    float acc[8][8];
    #pragma unroll
    for (int i = 0; i < 8; i++)
        #pragma unroll
        for (int j = 0; j < 8; j++) acc[i][j] = 0.0f;

    for (int k0 = 0; k0 < HDm; k0 += 8) {
        float4 av = *reinterpret_cast<const float4*>(Qb + (size_t)lrow * HDm + k0 + lcol);
        As[lcol+0][lrow] = av.x; As[lcol+1][lrow] = av.y;
        As[lcol+2][lrow] = av.z; As[lcol+3][lrow] = av.w;
        float4 bv = *reinterpret_cast<const float4*>(Kb + (size_t)lrow * HDm + k0 + lcol);
        Bs[lcol+0][lrow] = bv.x; Bs[lcol+1][lrow] = bv.y;
        Bs[lcol+2][lrow] = bv.z; Bs[lcol+3][lrow] = bv.w;
        __syncthreads();
        #pragma unroll
        for (int k = 0; k < 8; k++) {
            float4 a0 = *reinterpret_cast<const float4*>(&As[k][rm]);
            float4 a1 = *reinterpret_cast<const float4*>(&As[k][rm+4]);
            float4 b0 = *reinterpret_cast<const float4*>(&Bs[k][cn]);
            float4 b1 = *reinterpret_cast<const float4*>(&Bs[k][cn+4]);
            float ar[8] = {a0.x,a0.y,a0.z,a0.w,a1.x,a1.y,a1.z,a1.w};
            float br[8] = {b0.x,b0.y,b0.z,b0.w,b1.x,b1.y,b1.z,b1.w};
            #pragma unroll
            for (int i = 0; i < 8; i++)
                #pragma unroll
                for (int j = 0; j < 8; j++)
                    acc[i][j] = fmaf(ar[i], br[j], acc[i][j]);
        }
        __syncthreads();
    }

    int is32 = g_adj_is32;
    float mk[8];
    #pragma unroll
    for (int j = 0; j < 8; j++) mk[j] = mask[b * Nn + kt + cn + j];

    #pragma unroll
    for (int i = 0; i < 8; i++) {
        int q = qt + rm + i;
        float mq = mask[b * Nn + q];
        int arow = (b * Nn + q) * Nn;
        #pragma unroll
        for (int j = 0; j < 8; j++) {
            int k = kt + cn + j;
            int t = is32 ? adj32[arow + k] : adj32[2 * (arow + k)];
            float s = acc[i][j] * 0.125f + ebias[t * Hh + h];
            if (mq * mk[j] == 0.0f) s = -1e30f;
            S[(size_t)(bh * Nn + q) * Nn + k] = s;
        }
    }
}

// ---------------- softmax: one warp per row of 512, handles fully-masked rows ----
__global__ __launch_bounds__(256) void softmax_kernel(float* __restrict__ S)
{
    int warp = threadIdx.x >> 5, lane = threadIdx.x & 31;
    int row = blockIdx.x * 8 + warp;
    float* p = S + (size_t)row * Nn;
    float v[16];
    float mx = -3e30f;
    #pragma unroll
    for (int i = 0; i < 16; i++) { v[i] = p[i * 32 + lane]; mx = fmaxf(mx, v[i]); }
    #pragma unroll
    for (int o = 16; o; o >>= 1) mx = fmaxf(mx, __shfl_xor_sync(0xffffffffu, mx, o));
    if (mx < -1e29f) {   // fully masked row -> zeros (nan_to_num semantics)
        #pragma unroll
        for (int i = 0; i < 16; i++) p[i * 32 + lane] = 0.0f;
        return;
    }
    float s = 0.0f;
    #pragma unroll
    for (int i = 0; i < 16; i++) { v[i] = expf(v[i] - mx); s += v[i]; }
    #pragma unroll
    for (int o = 16; o; o >>= 1) s += __shfl_xor_sync(0xffffffffu, s, o);
    float inv = 1.0f / s;
    #pragma unroll
    for (int i = 0; i < 16; i++) p[i * 32 + lane] = v[i] * inv;
}

// ---------------- O = P @ V, per (b,h): 512x512 @ 512x64, writes (B,N,D) --------
__global__ __launch_bounds__(256) void pv_kernel(
    const float* __restrict__ S, const float* __restrict__ V, float* __restrict__ O)
{
    __shared__ float Ps[16][132];
    __shared__ float Vs[16][64];
    int tid = threadIdx.x;
    int bh = blockIdx.y, b = bh >> 3, h = bh & 7;
    int qt = blockIdx.x * 128;
    int rm = (tid >> 4) * 8, cn = (tid & 15) * 4;

    float acc[8][4];
    #pragma unroll
    for (int i = 0; i < 8; i++)
        #pragma unroll
        for (int j = 0; j < 4; j++) acc[i][j] = 0.0f;

    for (int k0 = 0; k0 < Nn; k0 += 16) {
        for (int e = tid; e < 2048; e += 256) {
            int r = e >> 4, c = e & 15;
            Ps[c][r] = S[(size_t)(bh * Nn + qt + r) * Nn + k0 + c];
        }
        for (int e = tid; e < 1024; e += 256) {
            int r = e >> 6, c = e & 63;
            Vs[r][c] = V[(size_t)(bh * Nn + k0 + r) * HDm + c];
        }
        __syncthreads();
        #pragma unroll
        for (int k = 0; k < 16; k++) {
            float4 a0 = *reinterpret_cast<const float4*>(&Ps[k][rm]);
            float4 a1 = *reinterpret_cast<const float4*>(&Ps[k][rm+4]);
            float4 b0 = *reinterpret_cast<const float4*>(&Vs[k][cn]);
            float ar[8] = {a0.x,a0.y,a0.z,a0.w,a1.x,a1.y,a1.z,a1.w};
            float br[4] = {b0.x,b0.y,b0.z,b0.w};
            #pragma unroll
            for (int i = 0; i < 8; i++)
                #pragma unroll
                for (int j = 0; j < 4; j++)
                    acc[i][j] = fmaf(ar[i], br[j], acc[i][j]);
        }
        __syncthreads();
    }

    #pragma unroll
    for (int i = 0; i < 8; i++) {
        int q = qt + rm + i;
        #pragma unroll
        for (int j = 0; j < 4; j++)
            O[(size_t)(b * Nn + q) * Dd + h * HDm + cn + j] = acc[i][j];
    }
}

// ---------------------------------- launch ----------------------------------
extern "C" void kernel_launch(void* const* d_in, const int* in_sizes, int n_in,
                              void* d_out, int out_size)
{
    const float* x    = (const float*)d_in[0];
    const int*   adj  = (const int*)  d_in[1];
    const float* mask = (const float*)d_in[2];
    const float* Wq   = (const float*)d_in[3];
    const float* bq   = (const float*)d_in[4];
    const float* Wk   = (const float*)d_in[5];
    const float* bk   = (const float*)d_in[6];
    const float* Wv   = (const float*)d_in[7];
    const float* bv   = (const float*)d_in[8];
    const float* Wo   = (const float*)d_in[9];
    const float* bo   = (const float*)d_in[10];
    const float* eb   = (const float*)d_in[11];
    const float* W1   = (const float*)d_in[12];
    const float* b1   = (const float*)d_in[13];
    const float* W2   = (const float*)d_in[14];
    const float* b2   = (const float*)d_in[15];
    const float* g1   = (const float*)d_in[16];
    const float* be1  = (const float*)d_in[17];
    const float* g2   = (const float*)d_in[18];
    const float* be2  = (const float*)d_in[19];
    float* out = (float*)d_out;

    float *h1, *Qb, *Kb, *Vb, *S, *O, *x1, *h2, *mid;
    cudaGetSymbolAddress((void**)&h1,  g_h1);
    cudaGetSymbolAddress((void**)&Qb,  g_Qb);
    cudaGetSymbolAddress((void**)&Kb,  g_Kb);
    cudaGetSymbolAddress((void**)&Vb,  g_Vb);
    cudaGetSymbolAddress((void**)&S,   g_S);
    cudaGetSymbolAddress((void**)&O,   g_O);
    cudaGetSymbolAddress((void**)&x1,  g_x1);
    cudaGetSymbolAddress((void**)&h2,  g_h2);
    cudaGetSymbolAddress((void**)&mid, g_mid);

    detect_adj_kernel<<<1, 256>>>(adj);

    // LN1
    ln_kernel<<<MR, 256>>>(x, g1, be1, h1);
    // QKV projections -> head layout (B,H,N,HD)
    sgemm_kernel<0><<<dim3(4, 64), 256>>>(h1, Wq, bq, nullptr, nullptr, Qb, MR, Dd, Dd);
    sgemm_kernel<0><<<dim3(4, 64), 256>>>(h1, Wk, bk, nullptr, nullptr, Kb, MR, Dd, Dd);
    sgemm_kernel<0><<<dim3(4, 64), 256>>>(h1, Wv, bv, nullptr, nullptr, Vb, MR, Dd, Dd);
    // scores + edge bias + mask
    score_kernel<<<dim3(4, 4, Bb * Hh), 256>>>(Qb, Kb, eb, adj, mask, S);
    // softmax
    softmax_kernel<<<(Bb * Hh * Nn) / 8, 256>>>(S);
    // P @ V -> (B,N,D)
    pv_kernel<<<dim3(4, Bb * Hh), 256>>>(S, Vb, O);
    // output projection + residual
    sgemm_kernel<1><<<dim3(4, 64), 256>>>(O, Wo, bo, x, nullptr, x1, MR, Dd, Dd);
    // LN2
    ln_kernel<<<MR, 256>>>(x1, g2, be2, h2);
    // FFN1 + exact gelu
    sgemm_kernel<2><<<dim3(16, 64), 256>>>(h2, W1, b1, nullptr, nullptr, mid, MR, DFF, Dd);
    // FFN2 + residual + final mask
    sgemm_kernel<3><<<dim3(4, 64), 256>>>(mid, W2, b2, x1, mask, out, MR, Dd, DFF);
}

// round 3
// speedup vs baseline: 2.6979x; 2.6979x over previous
#include <cuda_runtime.h>
#include <math.h>
#include <stdint.h>

#define Bb   16
#define Nn   512
#define Dd   512
#define Hh   8
#define HDm  64
#define MR   (Bb*Nn)     // 8192 rows
#define DFF  2048

// ---------------- scratch (static device globals; no allocation) ----------------
__device__ float g_h1 [MR*Dd];
__device__ float g_QKVb[3*MR*Dd];    // [3][B][H][N][HD]
__device__ float g_S  [Bb*Hh*Nn*Nn];
__device__ float g_O  [MR*Dd];       // (B,N,D)
__device__ float g_x1 [MR*Dd];
__device__ float g_h2 [MR*Dd];
__device__ float g_mid[MR*DFF];
__device__ float g_Wqkv[Dd*3*Dd];    // [512][1536] rounded, concat of Wq|Wk|Wv cols
__device__ float g_WoR [Dd*Dd];
__device__ float g_W1R [Dd*DFF];
__device__ float g_W2R [DFF*Dd];
__device__ float g_bqkv[3*Dd];
__device__ int   g_adj_is32;

// ======================= helpers =======================
__device__ __forceinline__ uint32_t smem_u32(const void* p) {
    uint32_t a;
    asm("{ .reg .u64 t; cvta.to.shared.u64 t, %1; cvt.u32.u64 %0, t; }" : "=r"(a) : "l"(p));
    return a;
}
__device__ __forceinline__ float f2tf32f(float f) {
    uint32_t u; asm("cvt.rna.tf32.f32 %0, %1;" : "=r"(u) : "f"(f));
    return __uint_as_float(u);
}
__device__ __forceinline__ void cp16(const float* s, const float* g) {
    uint32_t sa = smem_u32(s);
    asm volatile("cp.async.cg.shared.global [%0], [%1], 16;" :: "r"(sa), "l"(g) : "memory");
}
#define CP_COMMIT() asm volatile("cp.async.commit_group;" ::: "memory")
#define CP_WAIT(n)  asm volatile("cp.async.wait_group %0;" :: "n"(n) : "memory")

// m16n8k8 tf32 mma, row.col
__device__ __forceinline__ void mma8(float* c, const uint32_t* a, uint32_t b0, uint32_t b1) {
    asm volatile("mma.sync.aligned.m16n8k8.row.col.f32.tf32.tf32.f32 "
        "{%0,%1,%2,%3},{%4,%5,%6,%7},{%8,%9},{%0,%1,%2,%3};"
        : "+f"(c[0]), "+f"(c[1]), "+f"(c[2]), "+f"(c[3])
        : "r"(a[0]), "r"(a[1]), "r"(a[2]), "r"(a[3]), "r"(b0), "r"(b1));
}

// ======================= dense GEMM: C[M x ncols] = A @ W, tf32 mma =============
// CTA 128x128, 8 warps (4M x 2N), warp 32x64, KC=32 double-buffered cp.async.
// MODE 0: QKV scatter (+bias, tf32-round)   MODE 1: +bias +res
// MODE 2: gelu(+bias), tf32-round           MODE 3: (+bias +res)*mask[row]
#define DENSE_SMEM ((2*128*36 + 2*32*132)*4)

template<int MODE>
__global__ void __launch_bounds__(256, 1) mma_gemm(
    const float* __restrict__ A, const float* __restrict__ W,
    const float* __restrict__ bias, const float* __restrict__ res,
    const float* __restrict__ mask, float* __restrict__ C,
    int K, int ncols)
{
    extern __shared__ float sm[];
    float* sA = sm;                  // [2][128][36]
    float* sB = sm + 2*128*36;       // [2][32][132]
    const int tid = threadIdx.x, lane = tid & 31, warp = tid >> 5;
    const int wm = warp >> 1, wn = warp & 1, lq = lane >> 2, lr = lane & 3;
    const int bm = blockIdx.y * 128, bn = blockIdx.x * 128;

    float acc[2][8][4];
    #pragma unroll
    for (int i = 0; i < 2; i++)
        #pragma unroll
        for (int j = 0; j < 8; j++)
            #pragma unroll
            for (int l = 0; l < 4; l++) acc[i][j][l] = 0.0f;

    const int NC = K >> 5;

    // prologue loads
    #pragma unroll
    for (int pre = 0; pre < 2; pre++) {
        int k0 = pre * 32;
        float* dA = sA + pre * 4608;
        #pragma unroll
        for (int i = 0; i < 4; i++) {
            int cc = tid + i * 256, row = cc >> 3, seg = cc & 7;
            cp16(dA + row*36 + seg*4, A + (size_t)(bm + row) * K + k0 + seg*4);
        }
        float* dB = sB + pre * 4224;
        #pragma unroll
        for (int i = 0; i < 4; i++) {
            int cc = tid + i * 256, row = cc >> 5, seg = cc & 31;
            cp16(dB + row*132 + seg*4, W + (size_t)(k0 + row) * ncols + bn + seg*4);
        }
        CP_COMMIT();
    }

    for (int c = 0; c < NC; c++) {
        CP_WAIT(1);
        __syncthreads();
        const float* pA = sA + (c & 1) * 4608 + (wm * 32) * 36;
        const float* pB = sB + (c & 1) * 4224 + wn * 64;
        #pragma unroll
        for (int ks = 0; ks < 4; ks++) {
            uint32_t af[2][4];
            #pragma unroll
            for (int mt = 0; mt < 2; mt++) {
                int r = mt * 16 + lq;
                af[mt][0] = __float_as_uint(pA[r*36       + ks*8 + lr]);
                af[mt][1] = __float_as_uint(pA[(r+8)*36   + ks*8 + lr]);
                af[mt][2] = __float_as_uint(pA[r*36       + ks*8 + lr + 4]);
                af[mt][3] = __float_as_uint(pA[(r+8)*36   + ks*8 + lr + 4]);
            }
            #pragma unroll
            for (int nt = 0; nt < 8; nt++) {
                uint32_t b0 = __float_as_uint(pB[(ks*8 + lr)*132     + nt*8 + lq]);
                uint32_t b1 = __float_as_uint(pB[(ks*8 + lr + 4)*132 + nt*8 + lq]);
                mma8(acc[0][nt], af[0], b0, b1);
                mma8(acc[1][nt], af[1], b0, b1);
            }
        }
        __syncthreads();
        if (c + 2 < NC) {
            int k0 = (c + 2) * 32;
            float* dA = sA + (c & 1) * 4608;
            #pragma unroll
            for (int i = 0; i < 4; i++) {
                int cc = tid + i * 256, row = cc >> 3, seg = cc & 7;
                cp16(dA + row*36 + seg*4, A + (size_t)(bm + row) * K + k0 + seg*4);
            }
            float* dB = sB + (c & 1) * 4224;
            #pragma unroll
            for (int i = 0; i < 4; i++) {
                int cc = tid + i * 256, row = cc >> 5, seg = cc & 31;
                cp16(dB + row*132 + seg*4, W + (size_t)(k0 + row) * ncols + bn + seg*4);
            }
        }
        CP_COMMIT();
    }

    // ---------------- epilogue ----------------
    #pragma unroll
    for (int mt = 0; mt < 2; mt++) {
        #pragma unroll
        for (int half = 0; half < 2; half++) {
            int r = bm + wm*32 + mt*16 + lq + half*8;
            float mr = (MODE == 3) ? mask[r] : 0.0f;
            #pragma unroll
            for (int nt = 0; nt < 8; nt++) {
                int cg = bn + wn*64 + nt*8 + 2*lr;
                float v0 = acc[mt][nt][half*2 + 0] + bias[cg];
                float v1 = acc[mt][nt][half*2 + 1] + bias[cg + 1];
                if (MODE == 0) {
                    int mat = cg >> 9, cc = cg & 511, hh = cc >> 6, d0 = cc & 63;
                    int b = r >> 9, n = r & 511;
                    float* op = C + (((size_t)(mat*Bb + b)*Hh + hh)*Nn + n)*HDm + d0;
                    float2 o; o.x = f2tf32f(v0); o.y = f2tf32f(v1);
                    *reinterpret_cast<float2*>(op) = o;
                } else if (MODE == 1) {
                    const float* rp = res + (size_t)r * ncols + cg;
                    float2 r2 = *reinterpret_cast<const float2*>(rp);
                    float2 o; o.x = v0 + r2.x; o.y = v1 + r2.y;
                    *reinterpret_cast<float2*>(C + (size_t)r * ncols + cg) = o;
                } else if (MODE == 2) {
                    float2 o;
                    o.x = f2tf32f(0.5f * v0 * (1.0f + erff(v0 * 0.70710678118654752f)));
                    o.y = f2tf32f(0.5f * v1 * (1.0f + erff(v1 * 0.70710678118654752f)));
                    *reinterpret_cast<float2*>(C + (size_t)r * ncols + cg) = o;
                } else {
                    const float* rp = res + (size_t)r * ncols + cg;
                    float2 r2 = *reinterpret_cast<const float2*>(rp);
                    float2 o; o.x = (v0 + r2.x) * mr; o.y = (v1 + r2.y) * mr;
                    *reinterpret_cast<float2*>(C + (size_t)r * ncols + cg) = o;
                }
            }
        }
    }
}

// ======================= score: S = Q@K^T/8 + edge_bias, masked (tf32 mma) ======
#define SCORE_SMEM (2*128*68*4)
__global__ void __launch_bounds__(256, 1) score_mma(
    const float* __restrict__ Q, const float* __restrict__ Kt,
    const float* __restrict__ ebias, const int* __restrict__ adj32,
    const float* __restrict__ mask, float* __restrict__ S)
{
    extern __shared__ float sm[];
    float* sQ = sm;              // [128][68]
    float* sK = sm + 128*68;     // [128][68]
    const int tid = threadIdx.x, lane = tid & 31, warp = tid >> 5;
    const int wm = warp >> 1, wn = warp & 1, lq = lane >> 2, lr = lane & 3;
    const int bh = blockIdx.z, b = bh >> 3, h = bh & 7;
    const int qt = blockIdx.y * 128, kt = blockIdx.x * 128;

    #pragma unroll
    for (int i = 0; i < 8; i++) {
        int cc = tid + i * 256, row = cc >> 4, seg = cc & 15;
        cp16(sQ + row*68 + seg*4, Q  + (size_t)(bh*Nn + qt + row)*HDm + seg*4);
    }
    #pragma unroll
    for (int i = 0; i < 8; i++) {
        int cc = tid + i * 256, row = cc >> 4, seg = cc & 15;
        cp16(sK + row*68 + seg*4, Kt + (size_t)(bh*Nn + kt + row)*HDm + seg*4);
    }
    CP_COMMIT();
    CP_WAIT(0);
    __syncthreads();

    float acc[2][8][4];
    #pragma unroll
    for (int i = 0; i < 2; i++)
        #pragma unroll
        for (int j = 0; j < 8; j++)
            #pragma unroll
            for (int l = 0; l < 4; l++) acc[i][j][l] = 0.0f;

    const float* pQ = sQ + (wm * 32) * 68;
    const float* pK = sK + (wn * 64) * 68;
    #pragma unroll
    for (int ks = 0; ks < 8; ks++) {
        uint32_t af[2][4];
        #pragma unroll
        for (int mt = 0; mt < 2; mt++) {
            int r = mt * 16 + lq;
            af[mt][0] = __float_as_uint(pQ[r*68     + ks*8 + lr]);
            af[mt][1] = __float_as_uint(pQ[(r+8)*68 + ks*8 + lr]);
            af[mt][2] = __float_as_uint(pQ[r*68     + ks*8 + lr + 4]);
            af[mt][3] = __float_as_uint(pQ[(r+8)*68 + ks*8 + lr + 4]);
        }
        #pragma unroll
        for (int nt = 0; nt < 8; nt++) {
            uint32_t b0 = __float_as_uint(pK[(nt*8 + lq)*68 + ks*8 + lr]);
            uint32_t b1 = __float_as_uint(pK[(nt*8 + lq)*68 + ks*8 + lr + 4]);
            mma8(acc[0][nt], af[0], b0, b1);
            mma8(acc[1][nt], af[1], b0, b1);
        }
    }

    const int is32 = g_adj_is32;
    #pragma unroll
    for (int mt = 0; mt < 2; mt++) {
        #pragma unroll
        for (int half = 0; half < 2; half++) {
            int q = qt + wm*32 + mt*16 + lq + half*8;
            float mq = mask[b*Nn + q];
            int arow = (b*Nn + q) * Nn;
            #pragma unroll
            for (int nt = 0; nt < 8; nt++) {
                int k = kt + wn*64 + nt*8 + 2*lr;
                int t0 = is32 ? adj32[arow + k]     : adj32[2*(arow + k)];
                int t1 = is32 ? adj32[arow + k + 1] : adj32[2*(arow + k + 1)];
                float s0 = acc[mt][nt][half*2 + 0] * 0.125f + ebias[t0*Hh + h];
                float s1 = acc[mt][nt][half*2 + 1] * 0.125f + ebias[t1*Hh + h];
                if (mq * mask[b*Nn + k]     == 0.0f) s0 = -1e30f;
                if (mq * mask[b*Nn + k + 1] == 0.0f) s1 = -1e30f;
                float2 o; o.x = s0; o.y = s1;
                *reinterpret_cast<float2*>(S + (size_t)(bh*Nn + q)*Nn + k) = o;
            }
        }
    }
}

// ======================= PV: O = P@V (tf32 mma), out (B,N,D) rounded ============
#define PV_SMEM ((2*256*36 + 2*32*68)*4)
__global__ void __launch_bounds__(256, 1) pv_mma(
    const float* __restrict__ S, const float* __restrict__ V, float* __restrict__ O)
{
    extern __shared__ float sm[];
    float* sP = sm;                 // [2][256][36]
    float* sV = sm + 2*256*36;      // [2][32][68]
    const int tid = threadIdx.x, lane = tid & 31, warp = tid >> 5;
    const int lq = lane >> 2, lr = lane & 3;
    const int bh = blockIdx.y, b = bh >> 3, h = bh & 7;
    const int qt = blockIdx.x * 256;

    float acc[2][8][4];
    #pragma unroll
    for (int i = 0; i < 2; i++)
        #pragma unroll
        for (int j = 0; j < 8; j++)
            #pragma unroll
            for (int l = 0; l < 4; l++) acc[i][j][l] = 0.0f;

    #pragma unroll
    for (int pre = 0; pre < 2; pre++) {
        int k0 = pre * 32;
        float* dP = sP + pre * 9216;
        #pragma unroll
        for (int i = 0; i < 8; i++) {
            int cc = tid + i * 256, row = cc >> 3, seg = cc & 7;
            cp16(dP + row*36 + seg*4, S + (size_t)(bh*Nn + qt + row)*Nn + k0 + seg*4);
        }
        float* dV = sV + pre * 2176;
        #pragma unroll
        for (int i = 0; i < 2; i++) {
            int cc = tid + i * 256, row = cc >> 4, seg = cc & 15;
            cp16(dV + row*68 + seg*4, V + (size_t)(bh*Nn + k0 + row)*HDm + seg*4);
        }
        CP_COMMIT();
    }

    for (int c = 0; c < 16; c++) {
        CP_WAIT(1);
        __syncthreads();
        const float* pP = sP + (c & 1) * 9216 + (warp * 32) * 36;
        const float* pV = sV + (c & 1) * 2176;
        #pragma unroll
        for (int ks = 0; ks < 4; ks++) {
            uint32_t af[2][4];
            #pragma unroll
            for (int mt = 0; mt < 2; mt++) {
                int r = mt * 16 + lq;
                af[mt][0] = __float_as_uint(pP[r*36     + ks*8 + lr]);
                af[mt][1] = __float_as_uint(pP[(r+8)*36 + ks*8 + lr]);
                af[mt][2] = __float_as_uint(pP[r*36     + ks*8 + lr + 4]);
                af[mt][3] = __float_as_uint(pP[(r+8)*36 + ks*8 + lr + 4]);
            }
            #pragma unroll
            for (int nt = 0; nt < 8; nt++) {
                uint32_t b0 = __float_as_uint(pV[(ks*8 + lr)*68     + nt*8 + lq]);
                uint32_t b1 = __float_as_uint(pV[(ks*8 + lr + 4)*68 + nt*8 + lq]);
                mma8(acc[0][nt], af[0], b0, b1);
                mma8(acc[1][nt], af[1], b0, b1);
            }
        }
        __syncthreads();
        if (c + 2 < 16) {
            int k0 = (c + 2) * 32;
            float* dP = sP + (c & 1) * 9216;
            #pragma unroll
            for (int i = 0; i < 8; i++) {
                int cc = tid + i * 256, row = cc >> 3, seg = cc & 7;
                cp16(dP + row*36 + seg*4, S + (size_t)(bh*Nn + qt + row)*Nn + k0 + seg*4);
            }
            float* dV = sV + (c & 1) * 2176;
            #pragma unroll
            for (int i = 0; i < 2; i++) {
                int cc = tid + i * 256, row = cc >> 4, seg = cc & 15;
                cp16(dV + row*68 + seg*4, V + (size_t)(bh*Nn + k0 + row)*HDm + seg*4);
            }
        }
        CP_COMMIT();
    }

    #pragma unroll
    for (int mt = 0; mt < 2; mt++) {
        #pragma unroll
        for (int half = 0; half < 2; half++) {
            int q = qt + warp*32 + mt*16 + lq + half*8;
            #pragma unroll
            for (int nt = 0; nt < 8; nt++) {
                int d = nt*8 + 2*lr;
                float2 o;
                o.x = f2tf32f(acc[mt][nt][half*2 + 0]);
                o.y = f2tf32f(acc[mt][nt][half*2 + 1]);
                *reinterpret_cast<float2*>(O + (size_t)(b*Nn + q)*Dd + h*HDm + d) = o;
            }
        }
    }
}

// ---------------- weight rounding / packing ----------------
// dst[k*dstcols + off + n] = tf32_round(src[k*srccols + n])
__global__ void round_pack(const float* __restrict__ src, float* __restrict__ dst,
                           int srccols, int dstcols, int off, int total)
{
    int i = blockIdx.x * 256 + threadIdx.x;
    if (i >= total) return;
    int k = i / srccols, n = i - k * srccols;
    dst[(size_t)k * dstcols + off + n] = f2tf32f(src[i]);
}

__global__ void concat_bias_kernel(const float* __restrict__ a, const float* __restrict__ b,
                                   const float* __restrict__ c, float* __restrict__ o)
{
    int i = blockIdx.x * 256 + threadIdx.x;
    if (i < 512) o[i] = a[i];
    else if (i < 1024) o[i] = b[i - 512];
    else o[i] = c[i - 1024];
}

// ---------------- adj dtype detection (int32 vs int64) ----------------
__global__ void detect_adj_kernel(const int* __restrict__ a) {
    __shared__ int flag;
    if (threadIdx.x == 0) flag = 0;
    __syncthreads();
    for (int i = threadIdx.x; i < 8192; i += blockDim.x)
        if (a[2*i + 1] != 0) flag = 1;
    __syncthreads();
    if (threadIdx.x == 0) g_adj_is32 = flag;
}

// ---------------- LayerNorm (output tf32-rounded: feeds mma A operand) ----------
__global__ __launch_bounds__(256) void ln_kernel(
    const float* __restrict__ X, const float* __restrict__ g,
    const float* __restrict__ beta, float* __restrict__ Y)
{
    int row = blockIdx.x;
    const float* x = X + (size_t)row * Dd;
    int tid = threadIdx.x;
    float v0 = x[tid], v1 = x[tid + 256];

    __shared__ float red1[8], red2[8];
    float s = v0 + v1;
    #pragma unroll
    for (int o = 16; o; o >>= 1) s += __shfl_xor_sync(0xffffffffu, s, o);
    if ((tid & 31) == 0) red1[tid >> 5] = s;
    __syncthreads();
    float tot = red1[0]+red1[1]+red1[2]+red1[3]+red1[4]+red1[5]+red1[6]+red1[7];
    float mu = tot * (1.0f / 512.0f);

    float d0 = v0 - mu, d1 = v1 - mu;
    float s2 = d0*d0 + d1*d1;
    #pragma unroll
    for (int o = 16; o; o >>= 1) s2 += __shfl_xor_sync(0xffffffffu, s2, o);
    if ((tid & 31) == 0) red2[tid >> 5] = s2;
    __syncthreads();
    float tot2 = red2[0]+red2[1]+red2[2]+red2[3]+red2[4]+red2[5]+red2[6]+red2[7];
    float inv = rsqrtf(tot2 * (1.0f / 512.0f) + 1e-5f);

    Y[(size_t)row*Dd + tid      ] = f2tf32f(d0 * inv * g[tid      ] + beta[tid      ]);
    Y[(size_t)row*Dd + tid + 256] = f2tf32f(d1 * inv * g[tid + 256] + beta[tid + 256]);
}

// ---------------- softmax (in place on S, output tf32-rounded) ----------------
__global__ __launch_bounds__(256) void softmax_kernel(float* __restrict__ S)
{
    int warp = threadIdx.x >> 5, lane = threadIdx.x & 31;
    int row = blockIdx.x * 8 + warp;
    float* p = S + (size_t)row * Nn;
    float v[16];
    float mx = -3e30f;
    #pragma unroll
    for (int i = 0; i < 16; i++) { v[i] = p[i * 32 + lane]; mx = fmaxf(mx, v[i]); }
    #pragma unroll
    for (int o = 16; o; o >>= 1) mx = fmaxf(mx, __shfl_xor_sync(0xffffffffu, mx, o));
    if (mx < -1e29f) {
        #pragma unroll
        for (int i = 0; i < 16; i++) p[i * 32 + lane] = 0.0f;
        return;
    }
    float s = 0.0f;
    #pragma unroll
    for (int i = 0; i < 16; i++) { v[i] = expf(v[i] - mx); s += v[i]; }
    #pragma unroll
    for (int o = 16; o; o >>= 1) s += __shfl_xor_sync(0xffffffffu, s, o);
    float inv = 1.0f / s;
    #pragma unroll
    for (int i = 0; i < 16; i++) p[i * 32 + lane] = f2tf32f(v[i] * inv);
}

// ---------------------------------- launch ----------------------------------
extern "C" void kernel_launch(void* const* d_in, const int* in_sizes, int n_in,
                              void* d_out, int out_size)
{
    const float* x    = (const float*)d_in[0];
    const int*   adj  = (const int*)  d_in[1];
    const float* mask = (const float*)d_in[2];
    const float* Wq   = (const float*)d_in[3];
    const float* bq   = (const float*)d_in[4];
    const float* Wk   = (const float*)d_in[5];
    const float* bk   = (const float*)d_in[6];
    const float* Wv   = (const float*)d_in[7];
    const float* bv   = (const float*)d_in[8];
    const float* Wo   = (const float*)d_in[9];
    const float* bo   = (const float*)d_in[10];
    const float* eb   = (const float*)d_in[11];
    const float* W1   = (const float*)d_in[12];
    const float* b1   = (const float*)d_in[13];
    const float* W2   = (const float*)d_in[14];
    const float* b2   = (const float*)d_in[15];
    const float* g1   = (const float*)d_in[16];
    const float* be1  = (const float*)d_in[17];
    const float* g2   = (const float*)d_in[18];
    const float* be2  = (const float*)d_in[19];
    float* out = (float*)d_out;

    float *h1, *QKVb, *S, *O, *x1, *h2, *mid;
    float *Wqkv, *WoR, *W1R, *W2R, *bqkv;
    cudaGetSymbolAddress((void**)&h1,   g_h1);
    cudaGetSymbolAddress((void**)&QKVb, g_QKVb);
    cudaGetSymbolAddress((void**)&S,    g_S);
    cudaGetSymbolAddress((void**)&O,    g_O);
    cudaGetSymbolAddress((void**)&x1,   g_x1);
    cudaGetSymbolAddress((void**)&h2,   g_h2);
    cudaGetSymbolAddress((void**)&mid,  g_mid);
    cudaGetSymbolAddress((void**)&Wqkv, g_Wqkv);
    cudaGetSymbolAddress((void**)&WoR,  g_WoR);
    cudaGetSymbolAddress((void**)&W1R,  g_W1R);
    cudaGetSymbolAddress((void**)&W2R,  g_W2R);
    cudaGetSymbolAddress((void**)&bqkv, g_bqkv);

    static int attr_set = 0;
    if (!attr_set) {
        cudaFuncSetAttribute(mma_gemm<0>, cudaFuncAttributeMaxDynamicSharedMemorySize, DENSE_SMEM);
        cudaFuncSetAttribute(mma_gemm<1>, cudaFuncAttributeMaxDynamicSharedMemorySize, DENSE_SMEM);
        cudaFuncSetAttribute(mma_gemm<2>, cudaFuncAttributeMaxDynamicSharedMemorySize, DENSE_SMEM);
        cudaFuncSetAttribute(mma_gemm<3>, cudaFuncAttributeMaxDynamicSharedMemorySize, DENSE_SMEM);
        cudaFuncSetAttribute(score_mma,   cudaFuncAttributeMaxDynamicSharedMemorySize, SCORE_SMEM);
        cudaFuncSetAttribute(pv_mma,      cudaFuncAttributeMaxDynamicSharedMemorySize, PV_SMEM);
        attr_set = 1;
    }

    detect_adj_kernel<<<1, 256>>>(adj);

    // pre-round weights to tf32 (hw truncation then becomes exact)
    int tQ = Dd * Dd;
    round_pack<<<(tQ + 255)/256, 256>>>(Wq, Wqkv, Dd, 3*Dd, 0,    tQ);
    round_pack<<<(tQ + 255)/256, 256>>>(Wk, Wqkv, Dd, 3*Dd, 512,  tQ);
    round_pack<<<(tQ + 255)/256, 256>>>(Wv, Wqkv, Dd, 3*Dd, 1024, tQ);
    round_pack<<<(tQ + 255)/256, 256>>>(Wo, WoR,  Dd, Dd,   0,    tQ);
    int tF = Dd * DFF;
    round_pack<<<(tF + 255)/256, 256>>>(W1, W1R, DFF, DFF, 0, tF);
    round_pack<<<(tF + 255)/256, 256>>>(W2, W2R, Dd,  Dd,  0, tF);
    concat_bias_kernel<<<6, 256>>>(bq, bk, bv, bqkv);

    // LN1 (tf32-rounded out)
    ln_kernel<<<MR, 256>>>(x, g1, be1, h1);
    // fused QKV: [8192 x 512] @ [512 x 1536] -> head layout
    mma_gemm<0><<<dim3(12, 64), 256, DENSE_SMEM>>>(h1, Wqkv, bqkv, nullptr, nullptr, QKVb, Dd, 3*Dd);
    const float* Qp = QKVb;
    const float* Kp = QKVb + (size_t)MR * Dd;
    const float* Vp = QKVb + (size_t)2 * MR * Dd;
    // scores + edge bias + mask
    score_mma<<<dim3(4, 4, Bb * Hh), 256, SCORE_SMEM>>>(Qp, Kp, eb, adj, mask, S);
    softmax_kernel<<<(Bb * Hh * Nn) / 8, 256>>>(S);
    pv_mma<<<dim3(2, Bb * Hh), 256, PV_SMEM>>>(S, Vp, O);
    // output projection + residual
    mma_gemm<1><<<dim3(4, 64), 256, DENSE_SMEM>>>(O, WoR, bo, x, nullptr, x1, Dd, Dd);
    // LN2
    ln_kernel<<<MR, 256>>>(x1, g2, be2, h2);
    // FFN1 + exact gelu (tf32-rounded out)
    mma_gemm<2><<<dim3(16, 64), 256, DENSE_SMEM>>>(h2, W1R, b1, nullptr, nullptr, mid, Dd, DFF);
    // FFN2 + residual + final mask
    mma_gemm<3><<<dim3(4, 64), 256, DENSE_SMEM>>>(mid, W2R, b2, x1, mask, out, DFF, Dd);
}